// round 14
// baseline (speedup 1.0000x reference)
#include <cuda_runtime.h>
#include <cuda_bf16.h>
#include <cstdint>
#include <math.h>

// ---------------- problem constants ----------------
constexpr int NB    = 128;
constexpr int NC    = 23;
constexpr int NT    = 2000;
constexpr int NFFT  = 200;
constexpr int HOP   = 100;
constexpr int NFREQ = 101;
constexpr int FT    = 19;
constexpr int EMB   = 256;
constexpr int NHEADS= 8;
constexpr int DH    = 32;
constexpr int FFD   = 1024;
constexpr int SEQ   = NC * FT;        // 437
constexpr int NTOK  = NB * SEQ;       // 55936
constexpr int NFRAMES = NB * NC * FT; // 55936
constexpr int M2    = 2 * NFRAMES;    // 111872

// ---------------- scratch ----------------
__device__ float g_spec[M2 * NFREQ];
__device__ float g_h   [NTOK * EMB];
__device__ float g_qkv [NTOK * 768];
__device__ float g_ctx [NB * NHEADS * DH * DH];

__device__ __nv_bfloat16 g_hn_hi [NTOK * EMB];
__device__ __nv_bfloat16 g_hn_lo [NTOK * EMB];
__device__ __nv_bfloat16 g_at_hi [NTOK * EMB];
__device__ __nv_bfloat16 g_at_lo [NTOK * EMB];
__device__ __nv_bfloat16 g_ffn_hi[NTOK * FFD];
__device__ __nv_bfloat16 g_ffn_lo[NTOK * FFD];

__device__ __nv_bfloat16 g_wqkv_hi[4 * 768 * 256];
__device__ __nv_bfloat16 g_wqkv_lo[4 * 768 * 256];
__device__ __nv_bfloat16 g_wo_hi  [4 * 256 * 256];
__device__ __nv_bfloat16 g_wo_lo  [4 * 256 * 256];
__device__ __nv_bfloat16 g_w1_hi  [4 * 1024 * 256];
__device__ __nv_bfloat16 g_w1_lo  [4 * 1024 * 256];
__device__ __nv_bfloat16 g_w2_hi  [4 * 256 * 1024];
__device__ __nv_bfloat16 g_w2_lo  [4 * 256 * 1024];

// ---------------- base-ISA async-copy / mma helpers ----------------
__device__ __forceinline__ uint32_t smem_u32(const void* p) {
    uint32_t a;
    asm("{ .reg .u64 t; cvta.to.shared.u64 t, %1; cvt.u32.u64 %0, t; }" : "=r"(a) : "l"(p));
    return a;
}
__device__ __forceinline__ void cp16(uint32_t saddr, const void* gaddr) {
    asm volatile("cp.async.cg.shared.global [%0], [%1], 16;" :: "r"(saddr), "l"(gaddr));
}
#define CP_COMMIT() asm volatile("cp.async.commit_group;" ::: "memory")
#define CP_WAIT(n)  asm volatile("cp.async.wait_group %0;" :: "n"(n) : "memory")

__device__ __forceinline__ void ldsm4(uint32_t* r, uint32_t a) {
    asm volatile("ldmatrix.sync.aligned.m8n8.x4.shared.b16 {%0,%1,%2,%3}, [%4];"
                 : "=r"(r[0]), "=r"(r[1]), "=r"(r[2]), "=r"(r[3]) : "r"(a));
}
__device__ __forceinline__ void mma16816(float* d, const uint32_t* a, uint32_t b0, uint32_t b1) {
    asm volatile("mma.sync.aligned.m16n8k16.row.col.f32.bf16.bf16.f32 "
                 "{%0,%1,%2,%3}, {%4,%5,%6,%7}, {%8,%9}, {%0,%1,%2,%3};"
                 : "+f"(d[0]), "+f"(d[1]), "+f"(d[2]), "+f"(d[3])
                 : "r"(a[0]), "r"(a[1]), "r"(a[2]), "r"(a[3]), "r"(b0), "r"(b1));
}

__device__ __forceinline__ float gelu_f(float v) {
    float u = 1.5957691216057308f * (v + 0.044715f * v * v * v);
    return v / (1.0f + expf(-u));
}

// ---------------- tensor-core GEMM via mma.sync, bf16 hi/lo 3-term ----------------
// 512 threads, 16 warps as 4x4 grid, warp tile 32x32; 2-stage, 80KB smem.
// A stored [M,K] hi/lo; W stored [N,K] hi/lo.  out = [res +] act(A@W^T [+bias])
constexpr int BM = 128, BN = 128, BK = 32;
constexpr int LDS = 40;                       // padded smem stride (halves)
constexpr int MATH = BM * LDS;                // halves per matrix per stage (5120)
constexpr int STAGE_H = 4 * MATH;             // Ahi|Alo|Bhi|Blo (20480 halves)
constexpr uint32_t GSMEM = 2 * STAGE_H * 2;   // 81920 bytes
constexpr int GTHREADS = 512;

template<int K, int ACT, bool HASB, bool HASR, bool OUTBF>
__global__ __launch_bounds__(GTHREADS)
void gemm_mma(const __nv_bfloat16* __restrict__ Ahi, const __nv_bfloat16* __restrict__ Alo,
              const __nv_bfloat16* __restrict__ Whi, const __nv_bfloat16* __restrict__ Wlo,
              const float* __restrict__ bias, const float* __restrict__ res,
              float* __restrict__ outf, __nv_bfloat16* __restrict__ outhi, __nv_bfloat16* __restrict__ outlo,
              int ostride) {
    extern __shared__ __nv_bfloat16 sm[];

    const int tid  = threadIdx.x;
    const int warp = tid >> 5, lane = tid & 31;
    const int wm = warp & 3, wn = warp >> 2;          // 4x4 warps, warp tile 32x32
    const int m0 = blockIdx.y * BM;
    const int n0 = blockIdx.x * BN;

    constexpr int NCH = K / BK;
    static_assert(NCH >= 2, "K >= 64");

    float acc[2][4][4];
    #pragma unroll
    for (int i = 0; i < 2; i++)
        #pragma unroll
        for (int j = 0; j < 4; j++)
            #pragma unroll
            for (int t = 0; t < 4; t++) acc[i][j][t] = 0.f;

    auto load_stage = [&](int s, int c) {
        const int k = c * BK;
        __nv_bfloat16* base = sm + s * STAGE_H;
        int r = tid >> 2, sg = tid & 3;               // 128 rows x 4 segs, 1 cp16/matrix/thread
        uint32_t so = (uint32_t)(r * LDS + sg * 8);
        size_t ga = (size_t)(m0 + r) * K + k + sg * 8;
        size_t gb = (size_t)(n0 + r) * K + k + sg * 8;
        cp16(smem_u32(base + so),            Ahi + ga);
        cp16(smem_u32(base + MATH + so),     Alo + ga);
        cp16(smem_u32(base + 2 * MATH + so), Whi + gb);
        cp16(smem_u32(base + 3 * MATH + so), Wlo + gb);
        CP_COMMIT();
    };

    const int lr = lane & 15;       // ldmatrix row
    const int lc = lane >> 4;       // ldmatrix k-half

    auto compute_stage = [&](int s) {
        __nv_bfloat16* base = sm + s * STAGE_H;
        #pragma unroll
        for (int kk = 0; kk < BK; kk += 16) {
            uint32_t ahi[2][4], alo[2][4];
            #pragma unroll
            for (int mf = 0; mf < 2; mf++) {
                uint32_t ro = (uint32_t)((wm * 32 + mf * 16 + lr) * LDS + kk + lc * 8);
                ldsm4(ahi[mf], smem_u32(base + ro));
                ldsm4(alo[mf], smem_u32(base + MATH + ro));
            }
            uint32_t bhi[2][4], blo[2][4];
            #pragma unroll
            for (int nf2 = 0; nf2 < 2; nf2++) {
                uint32_t ro = (uint32_t)((wn * 32 + nf2 * 16 + lr) * LDS + kk + lc * 8);
                ldsm4(bhi[nf2], smem_u32(base + 2 * MATH + ro));
                ldsm4(blo[nf2], smem_u32(base + 3 * MATH + ro));
            }
            #pragma unroll
            for (int mf = 0; mf < 2; mf++)
                #pragma unroll
                for (int nf = 0; nf < 4; nf++) {
                    uint32_t h0 = bhi[nf >> 1][nf & 1], h1 = bhi[nf >> 1][(nf & 1) + 2];
                    uint32_t l0 = blo[nf >> 1][nf & 1], l1 = blo[nf >> 1][(nf & 1) + 2];
                    mma16816(acc[mf][nf], ahi[mf], h0, h1);
                    mma16816(acc[mf][nf], ahi[mf], l0, l1);
                    mma16816(acc[mf][nf], alo[mf], h0, h1);
                }
        }
    };

    load_stage(0, 0);
    for (int c = 0; c < NCH; c++) {
        if (c + 1 < NCH) {
            load_stage((c + 1) & 1, c + 1);
            CP_WAIT(1);
        } else {
            CP_WAIT(0);
        }
        __syncthreads();
        compute_stage(c & 1);
        __syncthreads();
    }

    // epilogue
    #pragma unroll
    for (int mf = 0; mf < 2; mf++) {
        #pragma unroll
        for (int nf = 0; nf < 4; nf++) {
            int row = m0 + wm * 32 + mf * 16 + (lane >> 2);
            int col = n0 + wn * 32 + nf * 8 + (lane & 3) * 2;
            #pragma unroll
            for (int half = 0; half < 2; half++) {
                int r = row + half * 8;
                #pragma unroll
                for (int j = 0; j < 2; j++) {
                    float v = acc[mf][nf][half * 2 + j];
                    int n = col + j;
                    if (HASB) v += bias[n];
                    if (ACT == 1) v = gelu_f(v);
                    size_t o = (size_t)r * ostride + n;
                    if (HASR) v += res[o];
                    if (OUTBF) {
                        __nv_bfloat16 hi = __float2bfloat16(v);
                        outhi[o] = hi;
                        outlo[o] = __float2bfloat16(v - __bfloat162float(hi));
                    } else {
                        outf[o] = v;
                    }
                }
            }
        }
    }
}

// ---------------- weight prep: tiled transpose + hi/lo split (verified win) ----------------
__global__ __launch_bounds__(256)
void prep_qkv(const float* __restrict__ Wq, const float* __restrict__ Wk,
              const float* __restrict__ Wv,
              __nv_bfloat16* __restrict__ hi, __nv_bfloat16* __restrict__ lo) {
    __shared__ float t[32][33];
    int l = blockIdx.z;
    int n0 = blockIdx.x * 32;       // over 768
    int k0 = blockIdx.y * 32;       // over 256
    int tx = threadIdx.x & 31, ty = threadIdx.x >> 5;
    const float* src = (n0 < 256) ? Wq : ((n0 < 512) ? Wk : Wv);
    int nc0 = n0 & 255;
    #pragma unroll
    for (int j = 0; j < 32; j += 8)
        t[ty + j][tx] = src[(size_t)l * 65536 + (k0 + ty + j) * 256 + nc0 + tx];
    __syncthreads();
    #pragma unroll
    for (int j = 0; j < 32; j += 8) {
        float w = t[tx][ty + j];    // (k = k0+tx, n = n0+ty+j)
        size_t o = (size_t)l * 768 * 256 + (size_t)(n0 + ty + j) * 256 + k0 + tx;
        __nv_bfloat16 h = __float2bfloat16(w);
        hi[o] = h; lo[o] = __float2bfloat16(w - __bfloat162float(h));
    }
}

__global__ __launch_bounds__(256)
void prep_w(const float* __restrict__ W, __nv_bfloat16* __restrict__ hi,
            __nv_bfloat16* __restrict__ lo, int Kd, int Nd) {
    __shared__ float t[32][33];
    int l = blockIdx.z;
    int n0 = blockIdx.x * 32;
    int k0 = blockIdx.y * 32;
    int tx = threadIdx.x & 31, ty = threadIdx.x >> 5;
    int tot = Kd * Nd;
    #pragma unroll
    for (int j = 0; j < 32; j += 8)
        t[ty + j][tx] = W[(size_t)l * tot + (size_t)(k0 + ty + j) * Nd + n0 + tx];
    __syncthreads();
    #pragma unroll
    for (int j = 0; j < 32; j += 8) {
        float w = t[tx][ty + j];
        size_t o = (size_t)l * tot + (size_t)(n0 + ty + j) * Kd + k0 + tx;
        __nv_bfloat16 h = __float2bfloat16(w);
        hi[o] = h; lo[o] = __float2bfloat16(w - __bfloat162float(h));
    }
}

// ---------------- STFT magnitude (exact DFT) ----------------
__global__ void stft_kernel(const float* __restrict__ x,
                            const unsigned int* __restrict__ mask,
                            float* __restrict__ spec) {
    __shared__ float frame[NFFT];
    __shared__ float ctab[NFFT];
    __shared__ float stab[NFFT];
    int bid = blockIdx.x;
    int variant = bid / NFRAMES;
    int rem = bid % NFRAMES;
    int f = rem % FT;
    int c = (rem / FT) % NC;
    int b = rem / (FT * NC);
    int base = (b * NC + c) * NT + f * HOP;

    for (int n = threadIdx.x; n < NFFT; n += blockDim.x) {
        float v = x[base + n];
        if (variant && (mask[base + n] != 0u)) v = 0.0f;
        frame[n] = v;
        float ang = 6.283185307179586f * (float)n / (float)NFFT;
        ctab[n] = cosf(ang);
        stab[n] = sinf(ang);
    }
    __syncthreads();

    int k = threadIdx.x;
    if (k < NFREQ) {
        float re = 0.f, im = 0.f;
        int m = 0;
        #pragma unroll 8
        for (int n = 0; n < NFFT; n++) {
            float fv = frame[n];
            re += fv * ctab[m];
            im += fv * stab[m];
            m += k;
            if (m >= NFFT) m -= NFFT;
        }
        spec[(size_t)bid * NFREQ + k] = sqrtf(re * re + im * im);
    }
}

// ---------------- embedding GEMM (K=101) + bias + channel tok + posenc ----------------
__global__ __launch_bounds__(256)
void embed_kernel(const float* __restrict__ Wp, const float* __restrict__ bp,
                  const float* __restrict__ ctok, const int* __restrict__ off,
                  float* __restrict__ out_c, float* __restrict__ out_m) {
    __shared__ float ssm[NFREQ][32];
    int row0 = blockIdx.x * 32;
    int tid = threadIdx.x;
    for (int i = tid; i < 32 * NFREQ; i += 256) {
        int r = i / NFREQ, k = i % NFREQ;
        ssm[k][r] = g_spec[(size_t)(row0 + r) * NFREQ + k];
    }
    __syncthreads();

    int n = tid;
    float acc[32];
    #pragma unroll
    for (int r = 0; r < 32; r++) acc[r] = 0.f;

    for (int k = 0; k < NFREQ; k++) {
        float w = Wp[k * EMB + n];
        const float4* a = reinterpret_cast<const float4*>(&ssm[k][0]);
        #pragma unroll
        for (int r4 = 0; r4 < 8; r4++) {
            float4 av = a[r4];
            acc[r4 * 4 + 0] += av.x * w;
            acc[r4 * 4 + 1] += av.y * w;
            acc[r4 * 4 + 2] += av.z * w;
            acc[r4 * 4 + 3] += av.w * w;
        }
    }

    float bias = bp[n];
    int i2 = n & ~1;
    float div = expf(-(float)i2 * (9.210340371976184f / (float)EMB));
    int o = *off;

    #pragma unroll
    for (int r = 0; r < 32; r++) {
        int grow = row0 + r;
        int variant = grow / NFRAMES;
        int rr = grow % NFRAMES;
        int f = rr % FT;
        int c = (rr / FT) % NC;
        int b = rr / (FT * NC);
        float sv, cv;
        sincosf((float)f * div, &sv, &cv);
        float pe = (n & 1) ? cv : sv;
        float val = acc[r] + bias + ctok[(c + o) * EMB + n] + pe;
        int token = b * SEQ + c * FT + f;
        float* dst = variant ? out_m : out_c;
        dst[(size_t)token * EMB + n] = val;
    }
}

// ---------------- LayerNorm -> bf16 hi/lo ----------------
__global__ __launch_bounds__(256)
void ln_kernel(const float* __restrict__ in, const float* __restrict__ g,
               const float* __restrict__ bta,
               __nv_bfloat16* __restrict__ ohi, __nv_bfloat16* __restrict__ olo) {
    int token = blockIdx.x;
    int tid = threadIdx.x;
    float v = in[(size_t)token * EMB + tid];
    __shared__ float red[18];
    float s = v, sq = v * v;
    #pragma unroll
    for (int o = 16; o > 0; o >>= 1) {
        s  += __shfl_xor_sync(0xffffffffu, s,  o);
        sq += __shfl_xor_sync(0xffffffffu, sq, o);
    }
    int wid = tid >> 5, lane = tid & 31;
    if (lane == 0) { red[wid] = s; red[8 + wid] = sq; }
    __syncthreads();
    if (tid == 0) {
        float ts = 0.f, tq = 0.f;
        #pragma unroll
        for (int i = 0; i < 8; i++) { ts += red[i]; tq += red[8 + i]; }
        red[16] = ts; red[17] = tq;
    }
    __syncthreads();
    float mean = red[16] * (1.0f / EMB);
    float var  = red[17] * (1.0f / EMB) - mean * mean;
    float y = (v - mean) * rsqrtf(var + 1e-5f) * g[tid] + bta[tid];
    size_t o = (size_t)token * EMB + tid;
    __nv_bfloat16 hi = __float2bfloat16(y);
    ohi[o] = hi;
    olo[o] = __float2bfloat16(y - __bfloat162float(hi));
}

// ---------------- ctx = softmax_seq(k)^T v per (b,h), k-softmax fused ----------------
__global__ __launch_bounds__(256)
void ctx_kernel(const float* __restrict__ qkv, float* __restrict__ ctx) {
    int h = blockIdx.x, b = blockIdx.y;
    __shared__ float ks[32][32];
    __shared__ float vs[32][32];
    __shared__ float rm[8][32];
    __shared__ float rs[8][32];
    __shared__ float fm[32];
    __shared__ float fi[32];
    int tid = threadIdx.x, warp = tid >> 5, lane = tid & 31;

    // pass 1: online max/sum over sequence per column (32 head dims)
    {
        float m = -1e30f, ssum = 0.f;
        for (int s = warp; s < SEQ; s += 8) {
            float v = qkv[((size_t)(b * SEQ + s)) * 768 + 256 + h * 32 + lane];
            float nm = fmaxf(m, v);
            ssum = ssum * expf(m - nm) + expf(v - nm);
            m = nm;
        }
        rm[warp][lane] = m; rs[warp][lane] = ssum;
    }
    __syncthreads();
    if (warp == 0) {
        float M = rm[0][lane], S = rs[0][lane];
        #pragma unroll
        for (int w = 1; w < 8; w++) {
            float m2 = rm[w][lane], s2 = rs[w][lane];
            float nm = fmaxf(M, m2);
            S = S * expf(M - nm) + s2 * expf(m2 - nm);
            M = nm;
        }
        fm[lane] = M; fi[lane] = 1.0f / S;
    }
    __syncthreads();

    // pass 2: accumulate softmax(k)^T v in 32-seq-row tiles
    int d  = tid >> 3;
    int e0 = (tid & 7) * 4;
    float acc[4] = {0.f, 0.f, 0.f, 0.f};
    for (int s0 = 0; s0 < SEQ; s0 += 32) {
        __syncthreads();
        #pragma unroll
        for (int j = 0; j < 4; j++) {
            int sr = warp + j * 8;
            int s = s0 + sr;
            float kv = 0.f, vv = 0.f;
            if (s < SEQ) {
                size_t idx = (size_t)(b * SEQ + s) * 768 + h * DH + lane;
                kv = qkv[idx + 256];
                vv = qkv[idx + 512];
            }
            ks[sr][lane] = expf(kv - fm[lane]) * fi[lane];  // vv=0 pads keep products 0
            vs[sr][lane] = vv;
        }
        __syncthreads();
        #pragma unroll
        for (int t = 0; t < 32; t++) {
            float kk = ks[t][d];
            #pragma unroll
            for (int j = 0; j < 4; j++) acc[j] += kk * vs[t][e0 + j];
        }
    }
    size_t ob = ((size_t)(b * NHEADS + h)) * DH * DH + d * DH + e0;
    #pragma unroll
    for (int j = 0; j < 4; j++) ctx[ob + j] = acc[j];
}

// ---------------- attn = softmax_dh(q)*scale @ ctx -> bf16 hi/lo, q-softmax fused ----------------
__global__ __launch_bounds__(256)
void attn_kernel(const float* __restrict__ qkv, const float* __restrict__ ctx,
                 __nv_bfloat16* __restrict__ ahi, __nv_bfloat16* __restrict__ alo) {
    int b = blockIdx.y;
    __shared__ float cs[NHEADS * DH * DH];
    int tid = threadIdx.x;
    for (int i = tid; i < NHEADS * DH * DH; i += 256)
        cs[i] = ctx[(size_t)b * NHEADS * DH * DH + i];
    __syncthreads();
    int h = tid >> 5, lane = tid & 31;
    for (int rr = 0; rr < 64; rr++) {
        int s = blockIdx.x * 64 + rr;
        if (s >= SEQ) break;
        size_t tok = (size_t)(b * SEQ + s);
        float qv = qkv[tok * 768 + h * DH + lane];
        float m = qv;
        #pragma unroll
        for (int o = 16; o > 0; o >>= 1) m = fmaxf(m, __shfl_xor_sync(0xffffffffu, m, o));
        float e = expf(qv - m);
        float su = e;
        #pragma unroll
        for (int o = 16; o > 0; o >>= 1) su += __shfl_xor_sync(0xffffffffu, su, o);
        float qn = e / su * 0.17677669529663687f;
        float acc = 0.f;
        #pragma unroll
        for (int d = 0; d < DH; d++)
            acc += __shfl_sync(0xffffffffu, qn, d) * cs[h * 1024 + d * 32 + lane];
        size_t o = tok * EMB + h * DH + lane;
        __nv_bfloat16 hi = __float2bfloat16(acc);
        ahi[o] = hi;
        alo[o] = __float2bfloat16(acc - __bfloat162float(hi));
    }
}

// ---------------- host orchestration ----------------
extern "C" void kernel_launch(void* const* d_in, const int* in_sizes, int n_in,
                              void* d_out, int out_size) {
    const float* x    = (const float*)d_in[0];
    const unsigned int* mask = (const unsigned int*)d_in[1];
    const int*   off  = (const int*)d_in[2];
    const float* Wp   = (const float*)d_in[3];
    const float* bp   = (const float*)d_in[4];
    const float* ctok = (const float*)d_in[5];
    const float* ln1g = (const float*)d_in[6];
    const float* ln1b = (const float*)d_in[7];
    const float* Wq   = (const float*)d_in[8];
    const float* Wk   = (const float*)d_in[9];
    const float* Wv   = (const float*)d_in[10];
    const float* Wo   = (const float*)d_in[11];
    const float* ln2g = (const float*)d_in[12];
    const float* ln2b = (const float*)d_in[13];
    const float* W1   = (const float*)d_in[14];
    const float* b1   = (const float*)d_in[15];
    const float* W2   = (const float*)d_in[16];
    const float* b2   = (const float*)d_in[17];
    float* out = (float*)d_out;

    cudaFuncSetAttribute(gemm_mma<256, 0, false, false, false>, cudaFuncAttributeMaxDynamicSharedMemorySize, GSMEM);
    cudaFuncSetAttribute(gemm_mma<256, 0, false, true, false>,  cudaFuncAttributeMaxDynamicSharedMemorySize, GSMEM);
    cudaFuncSetAttribute(gemm_mma<256, 1, true, false, true>,   cudaFuncAttributeMaxDynamicSharedMemorySize, GSMEM);
    cudaFuncSetAttribute(gemm_mma<1024, 0, true, true, false>,  cudaFuncAttributeMaxDynamicSharedMemorySize, GSMEM);

    void *p_spec, *p_h, *p_qkv, *p_ctx;
    void *p_hn_hi, *p_hn_lo, *p_at_hi, *p_at_lo, *p_ffn_hi, *p_ffn_lo;
    void *p_wqkv_hi, *p_wqkv_lo, *p_wo_hi, *p_wo_lo, *p_w1_hi, *p_w1_lo, *p_w2_hi, *p_w2_lo;
    cudaGetSymbolAddress(&p_spec, g_spec);
    cudaGetSymbolAddress(&p_h,    g_h);
    cudaGetSymbolAddress(&p_qkv,  g_qkv);
    cudaGetSymbolAddress(&p_ctx,  g_ctx);
    cudaGetSymbolAddress(&p_hn_hi, g_hn_hi);   cudaGetSymbolAddress(&p_hn_lo, g_hn_lo);
    cudaGetSymbolAddress(&p_at_hi, g_at_hi);   cudaGetSymbolAddress(&p_at_lo, g_at_lo);
    cudaGetSymbolAddress(&p_ffn_hi, g_ffn_hi); cudaGetSymbolAddress(&p_ffn_lo, g_ffn_lo);
    cudaGetSymbolAddress(&p_wqkv_hi, g_wqkv_hi); cudaGetSymbolAddress(&p_wqkv_lo, g_wqkv_lo);
    cudaGetSymbolAddress(&p_wo_hi, g_wo_hi);   cudaGetSymbolAddress(&p_wo_lo, g_wo_lo);
    cudaGetSymbolAddress(&p_w1_hi, g_w1_hi);   cudaGetSymbolAddress(&p_w1_lo, g_w1_lo);
    cudaGetSymbolAddress(&p_w2_hi, g_w2_hi);   cudaGetSymbolAddress(&p_w2_lo, g_w2_lo);

    float* h    = (float*)p_h;
    float* qkv  = (float*)p_qkv;
    float* ctx  = (float*)p_ctx;
    float* spec = (float*)p_spec;
    __nv_bfloat16 *hn_hi = (__nv_bfloat16*)p_hn_hi, *hn_lo = (__nv_bfloat16*)p_hn_lo;
    __nv_bfloat16 *at_hi = (__nv_bfloat16*)p_at_hi, *at_lo = (__nv_bfloat16*)p_at_lo;
    __nv_bfloat16 *ffn_hi = (__nv_bfloat16*)p_ffn_hi, *ffn_lo = (__nv_bfloat16*)p_ffn_lo;
    __nv_bfloat16 *wqkv_hi = (__nv_bfloat16*)p_wqkv_hi, *wqkv_lo = (__nv_bfloat16*)p_wqkv_lo;
    __nv_bfloat16 *wo_hi = (__nv_bfloat16*)p_wo_hi, *wo_lo = (__nv_bfloat16*)p_wo_lo;
    __nv_bfloat16 *w1_hi = (__nv_bfloat16*)p_w1_hi, *w1_lo = (__nv_bfloat16*)p_w1_lo;
    __nv_bfloat16 *w2_hi = (__nv_bfloat16*)p_w2_hi, *w2_lo = (__nv_bfloat16*)p_w2_lo;

    // 0) weight prep (tiled transpose to [N,K] + hi/lo split)
    prep_qkv<<<dim3(24, 8, 4), 256>>>(Wq, Wk, Wv, wqkv_hi, wqkv_lo);
    prep_w<<<dim3(8, 8, 4),  256>>>(Wo, wo_hi, wo_lo, 256, 256);
    prep_w<<<dim3(32, 8, 4), 256>>>(W1, w1_hi, w1_lo, 256, 1024);
    prep_w<<<dim3(8, 32, 4), 256>>>(W2, w2_hi, w2_lo, 1024, 256);

    // 1) STFT magnitudes (clean + masked)
    stft_kernel<<<2 * NFRAMES, 128>>>(x, mask, spec);

    // 2) embedding: emb_c -> out, emb_m -> h
    embed_kernel<<<M2 / 32, 256>>>(Wp, bp, ctok, off, out, h);

    // 3) transformer layers
    for (int l = 0; l < 4; l++) {
        ln_kernel<<<NTOK, 256>>>(h, ln1g + l * EMB, ln1b + l * EMB, hn_hi, hn_lo);

        gemm_mma<256, 0, false, false, false><<<dim3(6, NTOK / 128), GTHREADS, GSMEM>>>(
            hn_hi, hn_lo, wqkv_hi + (size_t)l * 768 * 256, wqkv_lo + (size_t)l * 768 * 256,
            nullptr, nullptr, qkv, nullptr, nullptr, 768);

        ctx_kernel<<<dim3(NHEADS, NB), 256>>>(qkv, ctx);
        attn_kernel<<<dim3((SEQ + 63) / 64, NB), 256>>>(qkv, ctx, at_hi, at_lo);

        gemm_mma<256, 0, false, true, false><<<dim3(2, NTOK / 128), GTHREADS, GSMEM>>>(
            at_hi, at_lo, wo_hi + (size_t)l * 65536, wo_lo + (size_t)l * 65536,
            nullptr, h, h, nullptr, nullptr, 256);

        ln_kernel<<<NTOK, 256>>>(h, ln2g + l * EMB, ln2b + l * EMB, hn_hi, hn_lo);

        gemm_mma<256, 1, true, false, true><<<dim3(8, NTOK / 128), GTHREADS, GSMEM>>>(
            hn_hi, hn_lo, w1_hi + (size_t)l * 262144, w1_lo + (size_t)l * 262144,
            b1 + (size_t)l * FFD, nullptr, nullptr, ffn_hi, ffn_lo, 1024);

        float* outH = (l == 3) ? (out + (size_t)NTOK * EMB) : h;
        gemm_mma<1024, 0, true, true, false><<<dim3(2, NTOK / 128), GTHREADS, GSMEM>>>(
            ffn_hi, ffn_lo, w2_hi + (size_t)l * 262144, w2_lo + (size_t)l * 262144,
            b2 + (size_t)l * EMB, h, outH, nullptr, nullptr, 256);
    }
}

// round 17
// speedup vs baseline: 1.1609x; 1.1609x over previous
#include <cuda_runtime.h>
#include <cuda_bf16.h>
#include <cstdint>
#include <math.h>

// ---------------- problem constants ----------------
constexpr int NB    = 128;
constexpr int NC    = 23;
constexpr int NT    = 2000;
constexpr int NFFT  = 200;
constexpr int HOP   = 100;
constexpr int NFREQ = 101;
constexpr int FT    = 19;
constexpr int EMB   = 256;
constexpr int NHEADS= 8;
constexpr int DH    = 32;
constexpr int FFD   = 1024;
constexpr int SEQ   = NC * FT;        // 437
constexpr int NTOK  = NB * SEQ;       // 55936
constexpr int NFRAMES = NB * NC * FT; // 55936
constexpr int M2    = 2 * NFRAMES;    // 111872

// ---------------- scratch ----------------
__device__ float g_spec[M2 * NFREQ];
__device__ float g_h   [NTOK * EMB];
__device__ float g_qkv [NTOK * 768];
__device__ float g_ctx [NB * NHEADS * DH * DH];
__device__ float g_ctab[NFFT];
__device__ float g_stab[NFFT];
__device__ float g_pe  [FT * EMB];

__device__ __nv_bfloat16 g_hn_hi [NTOK * EMB];
__device__ __nv_bfloat16 g_hn_lo [NTOK * EMB];
__device__ __nv_bfloat16 g_at_hi [NTOK * EMB];
__device__ __nv_bfloat16 g_at_lo [NTOK * EMB];
__device__ __nv_bfloat16 g_ffn_hi[NTOK * FFD];
__device__ __nv_bfloat16 g_ffn_lo[NTOK * FFD];

__device__ __nv_bfloat16 g_wqkv_hi[4 * 768 * 256];
__device__ __nv_bfloat16 g_wqkv_lo[4 * 768 * 256];
__device__ __nv_bfloat16 g_wo_hi  [4 * 256 * 256];
__device__ __nv_bfloat16 g_wo_lo  [4 * 256 * 256];
__device__ __nv_bfloat16 g_w1_hi  [4 * 1024 * 256];
__device__ __nv_bfloat16 g_w1_lo  [4 * 1024 * 256];
__device__ __nv_bfloat16 g_w2_hi  [4 * 256 * 1024];
__device__ __nv_bfloat16 g_w2_lo  [4 * 256 * 1024];

// ---------------- base-ISA async-copy / mma helpers ----------------
__device__ __forceinline__ uint32_t smem_u32(const void* p) {
    uint32_t a;
    asm("{ .reg .u64 t; cvta.to.shared.u64 t, %1; cvt.u32.u64 %0, t; }" : "=r"(a) : "l"(p));
    return a;
}
__device__ __forceinline__ void cp16(uint32_t saddr, const void* gaddr) {
    asm volatile("cp.async.cg.shared.global [%0], [%1], 16;" :: "r"(saddr), "l"(gaddr));
}
#define CP_COMMIT() asm volatile("cp.async.commit_group;" ::: "memory")
#define CP_WAIT(n)  asm volatile("cp.async.wait_group %0;" :: "n"(n) : "memory")

__device__ __forceinline__ void ldsm4(uint32_t* r, uint32_t a) {
    asm volatile("ldmatrix.sync.aligned.m8n8.x4.shared.b16 {%0,%1,%2,%3}, [%4];"
                 : "=r"(r[0]), "=r"(r[1]), "=r"(r[2]), "=r"(r[3]) : "r"(a));
}
__device__ __forceinline__ void mma16816(float* d, const uint32_t* a, uint32_t b0, uint32_t b1) {
    asm volatile("mma.sync.aligned.m16n8k16.row.col.f32.bf16.bf16.f32 "
                 "{%0,%1,%2,%3}, {%4,%5,%6,%7}, {%8,%9}, {%0,%1,%2,%3};"
                 : "+f"(d[0]), "+f"(d[1]), "+f"(d[2]), "+f"(d[3])
                 : "r"(a[0]), "r"(a[1]), "r"(a[2]), "r"(a[3]), "r"(b0), "r"(b1));
}

__device__ __forceinline__ float gelu_f(float v) {
    float u = 1.5957691216057308f * (v + 0.044715f * v * v * v);
    return v / (1.0f + expf(-u));
}

// ---------------- table init (twiddles + posenc) ----------------
__global__ void init_tables() {
    int i = blockIdx.x * 256 + threadIdx.x;
    if (i < NFFT) {
        float ang = 6.283185307179586f * (float)i / (float)NFFT;
        g_ctab[i] = cosf(ang);
        g_stab[i] = sinf(ang);
    }
    if (i < FT * EMB) {
        int f = i / EMB, n = i % EMB;
        int i2 = n & ~1;
        float div = expf(-(float)i2 * (9.210340371976184f / (float)EMB));
        float sv, cv;
        sincosf((float)f * div, &sv, &cv);
        g_pe[i] = (n & 1) ? cv : sv;
    }
}

// ---------------- tensor-core GEMM via mma.sync, bf16 hi/lo 3-term ----------------
// EXACT R9/R12 configuration (measured 7474us): 256 thr, 2-stage, 80KB smem, warp tile 32x64.
constexpr int BM = 128, BN = 128, BK = 32;
constexpr int LDS = 40;                       // padded smem stride (halves)
constexpr int MATH = BM * LDS;                // halves per matrix per stage (5120)
constexpr int STAGE_H = 4 * MATH;             // Ahi|Alo|Bhi|Blo (20480 halves)
constexpr uint32_t GSMEM = 2 * STAGE_H * 2;   // 81920 bytes

template<int K, int ACT, bool HASB, bool HASR, bool OUTBF>
__global__ __launch_bounds__(256)
void gemm_mma(const __nv_bfloat16* __restrict__ Ahi, const __nv_bfloat16* __restrict__ Alo,
              const __nv_bfloat16* __restrict__ Whi, const __nv_bfloat16* __restrict__ Wlo,
              const float* __restrict__ bias, const float* __restrict__ res,
              float* __restrict__ outf, __nv_bfloat16* __restrict__ outhi, __nv_bfloat16* __restrict__ outlo,
              int ostride) {
    extern __shared__ __nv_bfloat16 sm[];

    const int tid  = threadIdx.x;
    const int warp = tid >> 5, lane = tid & 31;
    const int wm = warp & 3, wn = warp >> 2;          // 4x2 warps, warp tile 32x64
    const int m0 = blockIdx.y * BM;
    const int n0 = blockIdx.x * BN;

    constexpr int NCH = K / BK;
    static_assert(NCH >= 2, "K >= 64");

    float acc[2][8][4];
    #pragma unroll
    for (int i = 0; i < 2; i++)
        #pragma unroll
        for (int j = 0; j < 8; j++)
            #pragma unroll
            for (int t = 0; t < 4; t++) acc[i][j][t] = 0.f;

    auto load_stage = [&](int s, int c) {
        const int k = c * BK;
        __nv_bfloat16* base = sm + s * STAGE_H;
        #pragma unroll
        for (int i = 0; i < 2; i++) {
            int id = tid + i * 256;
            int r = id >> 2, sg = id & 3;
            uint32_t so = (uint32_t)(r * LDS + sg * 8);
            size_t ga = (size_t)(m0 + r) * K + k + sg * 8;
            size_t gb = (size_t)(n0 + r) * K + k + sg * 8;
            cp16(smem_u32(base + so),            Ahi + ga);
            cp16(smem_u32(base + MATH + so),     Alo + ga);
            cp16(smem_u32(base + 2 * MATH + so), Whi + gb);
            cp16(smem_u32(base + 3 * MATH + so), Wlo + gb);
        }
        CP_COMMIT();
    };

    const int lr = lane & 15;       // ldmatrix row
    const int lc = lane >> 4;       // ldmatrix k-half

    auto compute_stage = [&](int s) {
        __nv_bfloat16* base = sm + s * STAGE_H;
        #pragma unroll
        for (int kk = 0; kk < BK; kk += 16) {
            uint32_t ahi[2][4], alo[2][4];
            #pragma unroll
            for (int mf = 0; mf < 2; mf++) {
                uint32_t ro = (uint32_t)((wm * 32 + mf * 16 + lr) * LDS + kk + lc * 8);
                ldsm4(ahi[mf], smem_u32(base + ro));
                ldsm4(alo[mf], smem_u32(base + MATH + ro));
            }
            uint32_t bhi[4][4], blo[4][4];
            #pragma unroll
            for (int nf2 = 0; nf2 < 4; nf2++) {
                uint32_t ro = (uint32_t)((wn * 64 + nf2 * 16 + lr) * LDS + kk + lc * 8);
                ldsm4(bhi[nf2], smem_u32(base + 2 * MATH + ro));
                ldsm4(blo[nf2], smem_u32(base + 3 * MATH + ro));
            }
            #pragma unroll
            for (int mf = 0; mf < 2; mf++)
                #pragma unroll
                for (int nf = 0; nf < 8; nf++) {
                    uint32_t h0 = bhi[nf >> 1][nf & 1], h1 = bhi[nf >> 1][(nf & 1) + 2];
                    uint32_t l0 = blo[nf >> 1][nf & 1], l1 = blo[nf >> 1][(nf & 1) + 2];
                    mma16816(acc[mf][nf], ahi[mf], h0, h1);
                    mma16816(acc[mf][nf], ahi[mf], l0, l1);
                    mma16816(acc[mf][nf], alo[mf], h0, h1);
                }
        }
    };

    load_stage(0, 0);
    for (int c = 0; c < NCH; c++) {
        if (c + 1 < NCH) {
            load_stage((c + 1) & 1, c + 1);
            CP_WAIT(1);
        } else {
            CP_WAIT(0);
        }
        __syncthreads();
        compute_stage(c & 1);
        __syncthreads();
    }

    // epilogue
    #pragma unroll
    for (int mf = 0; mf < 2; mf++) {
        #pragma unroll
        for (int nf = 0; nf < 8; nf++) {
            int row = m0 + wm * 32 + mf * 16 + (lane >> 2);
            int col = n0 + wn * 64 + nf * 8 + (lane & 3) * 2;
            #pragma unroll
            for (int half = 0; half < 2; half++) {
                int r = row + half * 8;
                #pragma unroll
                for (int j = 0; j < 2; j++) {
                    float v = acc[mf][nf][half * 2 + j];
                    int n = col + j;
                    if (HASB) v += bias[n];
                    if (ACT == 1) v = gelu_f(v);
                    size_t o = (size_t)r * ostride + n;
                    if (HASR) v += res[o];
                    if (OUTBF) {
                        __nv_bfloat16 hi = __float2bfloat16(v);
                        outhi[o] = hi;
                        outlo[o] = __float2bfloat16(v - __bfloat162float(hi));
                    } else {
                        outf[o] = v;
                    }
                }
            }
        }
    }
}

// ---------------- weight prep: tiled transpose + hi/lo split (verified win) ----------------
__global__ __launch_bounds__(256)
void prep_qkv(const float* __restrict__ Wq, const float* __restrict__ Wk,
              const float* __restrict__ Wv,
              __nv_bfloat16* __restrict__ hi, __nv_bfloat16* __restrict__ lo) {
    __shared__ float t[32][33];
    int l = blockIdx.z;
    int n0 = blockIdx.x * 32;       // over 768
    int k0 = blockIdx.y * 32;       // over 256
    int tx = threadIdx.x & 31, ty = threadIdx.x >> 5;
    const float* src = (n0 < 256) ? Wq : ((n0 < 512) ? Wk : Wv);
    int nc0 = n0 & 255;
    #pragma unroll
    for (int j = 0; j < 32; j += 8)
        t[ty + j][tx] = src[(size_t)l * 65536 + (k0 + ty + j) * 256 + nc0 + tx];
    __syncthreads();
    #pragma unroll
    for (int j = 0; j < 32; j += 8) {
        float w = t[tx][ty + j];    // (k = k0+tx, n = n0+ty+j)
        size_t o = (size_t)l * 768 * 256 + (size_t)(n0 + ty + j) * 256 + k0 + tx;
        __nv_bfloat16 h = __float2bfloat16(w);
        hi[o] = h; lo[o] = __float2bfloat16(w - __bfloat162float(h));
    }
}

__global__ __launch_bounds__(256)
void prep_w(const float* __restrict__ W, __nv_bfloat16* __restrict__ hi,
            __nv_bfloat16* __restrict__ lo, int Kd, int Nd) {
    __shared__ float t[32][33];
    int l = blockIdx.z;
    int n0 = blockIdx.x * 32;
    int k0 = blockIdx.y * 32;
    int tx = threadIdx.x & 31, ty = threadIdx.x >> 5;
    int tot = Kd * Nd;
    #pragma unroll
    for (int j = 0; j < 32; j += 8)
        t[ty + j][tx] = W[(size_t)l * tot + (size_t)(k0 + ty + j) * Nd + n0 + tx];
    __syncthreads();
    #pragma unroll
    for (int j = 0; j < 32; j += 8) {
        float w = t[tx][ty + j];
        size_t o = (size_t)l * tot + (size_t)(n0 + ty + j) * Kd + k0 + tx;
        __nv_bfloat16 h = __float2bfloat16(w);
        hi[o] = h; lo[o] = __float2bfloat16(w - __bfloat162float(h));
    }
}

// ---------------- STFT magnitude (exact DFT, precomputed twiddles) ----------------
__global__ void stft_kernel(const float* __restrict__ x,
                            const unsigned int* __restrict__ mask,
                            float* __restrict__ spec) {
    __shared__ float frame[NFFT];
    __shared__ float ctab[NFFT];
    __shared__ float stab[NFFT];
    int bid = blockIdx.x;
    int variant = bid / NFRAMES;
    int rem = bid % NFRAMES;
    int f = rem % FT;
    int c = (rem / FT) % NC;
    int b = rem / (FT * NC);
    int base = (b * NC + c) * NT + f * HOP;

    for (int n = threadIdx.x; n < NFFT; n += blockDim.x) {
        float v = x[base + n];
        if (variant && (mask[base + n] != 0u)) v = 0.0f;
        frame[n] = v;
        ctab[n] = g_ctab[n];
        stab[n] = g_stab[n];
    }
    __syncthreads();

    int k = threadIdx.x;
    if (k < NFREQ) {
        float re = 0.f, im = 0.f;
        int m = 0;
        #pragma unroll 8
        for (int n = 0; n < NFFT; n++) {
            float fv = frame[n];
            re += fv * ctab[m];
            im += fv * stab[m];
            m += k;
            if (m >= NFFT) m -= NFFT;
        }
        spec[(size_t)bid * NFREQ + k] = sqrtf(re * re + im * im);
    }
}

// ---------------- embedding GEMM (K=101) + bias + channel tok + posenc (table) ----------------
__global__ __launch_bounds__(256)
void embed_kernel(const float* __restrict__ Wp, const float* __restrict__ bp,
                  const float* __restrict__ ctok, const int* __restrict__ off,
                  float* __restrict__ out_c, float* __restrict__ out_m) {
    __shared__ float ssm[NFREQ][32];
    int row0 = blockIdx.x * 32;
    int tid = threadIdx.x;
    for (int i = tid; i < 32 * NFREQ; i += 256) {
        int r = i / NFREQ, k = i % NFREQ;
        ssm[k][r] = g_spec[(size_t)(row0 + r) * NFREQ + k];
    }
    __syncthreads();

    int n = tid;
    float acc[32];
    #pragma unroll
    for (int r = 0; r < 32; r++) acc[r] = 0.f;

    for (int k = 0; k < NFREQ; k++) {
        float w = Wp[k * EMB + n];
        const float4* a = reinterpret_cast<const float4*>(&ssm[k][0]);
        #pragma unroll
        for (int r4 = 0; r4 < 8; r4++) {
            float4 av = a[r4];
            acc[r4 * 4 + 0] += av.x * w;
            acc[r4 * 4 + 1] += av.y * w;
            acc[r4 * 4 + 2] += av.z * w;
            acc[r4 * 4 + 3] += av.w * w;
        }
    }

    float bias = bp[n];
    int o = *off;

    #pragma unroll
    for (int r = 0; r < 32; r++) {
        int grow = row0 + r;
        int variant = grow / NFRAMES;
        int rr = grow % NFRAMES;
        int f = rr % FT;
        int c = (rr / FT) % NC;
        int b = rr / (FT * NC);
        float pe = g_pe[f * EMB + n];
        float val = acc[r] + bias + ctok[(c + o) * EMB + n] + pe;
        int token = b * SEQ + c * FT + f;
        float* dst = variant ? out_m : out_c;
        dst[(size_t)token * EMB + n] = val;
    }
}

// ---------------- LayerNorm -> bf16 hi/lo (warp per token) ----------------
__global__ __launch_bounds__(256)
void ln_kernel(const float* __restrict__ in, const float* __restrict__ g,
               const float* __restrict__ bta,
               __nv_bfloat16* __restrict__ ohi, __nv_bfloat16* __restrict__ olo) {
    int warp = threadIdx.x >> 5, lane = threadIdx.x & 31;
    int token = blockIdx.x * 8 + warp;
    size_t base = (size_t)token * EMB + lane * 8;
    float4 a = *reinterpret_cast<const float4*>(in + base);
    float4 b = *reinterpret_cast<const float4*>(in + base + 4);
    float v[8] = {a.x, a.y, a.z, a.w, b.x, b.y, b.z, b.w};
    float s = 0.f, sq = 0.f;
    #pragma unroll
    for (int j = 0; j < 8; j++) { s += v[j]; sq += v[j] * v[j]; }
    #pragma unroll
    for (int o = 16; o > 0; o >>= 1) {
        s  += __shfl_xor_sync(0xffffffffu, s,  o);
        sq += __shfl_xor_sync(0xffffffffu, sq, o);
    }
    float mean = s * (1.0f / EMB);
    float var  = sq * (1.0f / EMB) - mean * mean;
    float rstd = rsqrtf(var + 1e-5f);

    float4 g0 = *reinterpret_cast<const float4*>(g + lane * 8);
    float4 g1 = *reinterpret_cast<const float4*>(g + lane * 8 + 4);
    float4 b0 = *reinterpret_cast<const float4*>(bta + lane * 8);
    float4 b1 = *reinterpret_cast<const float4*>(bta + lane * 8 + 4);
    float gg[8] = {g0.x, g0.y, g0.z, g0.w, g1.x, g1.y, g1.z, g1.w};
    float bb[8] = {b0.x, b0.y, b0.z, b0.w, b1.x, b1.y, b1.z, b1.w};

    union { __nv_bfloat162 v[4]; uint4 u; } H, L;
    #pragma unroll
    for (int j = 0; j < 4; j++) {
        float y0 = (v[2 * j]     - mean) * rstd * gg[2 * j]     + bb[2 * j];
        float y1 = (v[2 * j + 1] - mean) * rstd * gg[2 * j + 1] + bb[2 * j + 1];
        __nv_bfloat16 h0 = __float2bfloat16(y0);
        __nv_bfloat16 h1 = __float2bfloat16(y1);
        H.v[j] = __nv_bfloat162(h0, h1);
        L.v[j] = __nv_bfloat162(__float2bfloat16(y0 - __bfloat162float(h0)),
                                __float2bfloat16(y1 - __bfloat162float(h1)));
    }
    *reinterpret_cast<uint4*>(ohi + base) = H.u;
    *reinterpret_cast<uint4*>(olo + base) = L.u;
}

// ---------------- ctx = softmax_seq(k)^T v per (b,h), k-softmax fused ----------------
__global__ __launch_bounds__(256)
void ctx_kernel(const float* __restrict__ qkv, float* __restrict__ ctx) {
    int h = blockIdx.x, b = blockIdx.y;
    __shared__ float ks[32][32];
    __shared__ float vs[32][32];
    __shared__ float rm[8][32];
    __shared__ float rs[8][32];
    __shared__ float fm[32];
    __shared__ float fi[32];
    int tid = threadIdx.x, warp = tid >> 5, lane = tid & 31;

    // pass 1: online max/sum over sequence per column (32 head dims)
    {
        float m = -1e30f, ssum = 0.f;
        for (int s = warp; s < SEQ; s += 8) {
            float v = qkv[((size_t)(b * SEQ + s)) * 768 + 256 + h * 32 + lane];
            float nm = fmaxf(m, v);
            ssum = ssum * expf(m - nm) + expf(v - nm);
            m = nm;
        }
        rm[warp][lane] = m; rs[warp][lane] = ssum;
    }
    __syncthreads();
    if (warp == 0) {
        float M = rm[0][lane], S = rs[0][lane];
        #pragma unroll
        for (int w = 1; w < 8; w++) {
            float m2 = rm[w][lane], s2 = rs[w][lane];
            float nm = fmaxf(M, m2);
            S = S * expf(M - nm) + s2 * expf(m2 - nm);
            M = nm;
        }
        fm[lane] = M; fi[lane] = 1.0f / S;
    }
    __syncthreads();

    // pass 2: accumulate softmax(k)^T v in 32-seq-row tiles
    int d  = tid >> 3;
    int e0 = (tid & 7) * 4;
    float acc[4] = {0.f, 0.f, 0.f, 0.f};
    for (int s0 = 0; s0 < SEQ; s0 += 32) {
        __syncthreads();
        #pragma unroll
        for (int j = 0; j < 4; j++) {
            int sr = warp + j * 8;
            int s = s0 + sr;
            float kv = 0.f, vv = 0.f;
            if (s < SEQ) {
                size_t idx = (size_t)(b * SEQ + s) * 768 + h * DH + lane;
                kv = qkv[idx + 256];
                vv = qkv[idx + 512];
            }
            ks[sr][lane] = expf(kv - fm[lane]) * fi[lane];  // vv=0 pads keep products 0
            vs[sr][lane] = vv;
        }
        __syncthreads();
        #pragma unroll
        for (int t = 0; t < 32; t++) {
            float kk = ks[t][d];
            #pragma unroll
            for (int j = 0; j < 4; j++) acc[j] += kk * vs[t][e0 + j];
        }
    }
    size_t ob = ((size_t)(b * NHEADS + h)) * DH * DH + d * DH + e0;
    #pragma unroll
    for (int j = 0; j < 4; j++) ctx[ob + j] = acc[j];
}

// ---------------- attn = softmax_dh(q)*scale @ ctx -> bf16 hi/lo, q-softmax fused ----------------
__global__ __launch_bounds__(256)
void attn_kernel(const float* __restrict__ qkv, const float* __restrict__ ctx,
                 __nv_bfloat16* __restrict__ ahi, __nv_bfloat16* __restrict__ alo) {
    int b = blockIdx.y;
    __shared__ float cs[NHEADS * DH * DH];
    int tid = threadIdx.x;
    for (int i = tid; i < NHEADS * DH * DH; i += 256)
        cs[i] = ctx[(size_t)b * NHEADS * DH * DH + i];
    __syncthreads();
    int h = tid >> 5, lane = tid & 31;
    for (int rr = 0; rr < 64; rr++) {
        int s = blockIdx.x * 64 + rr;
        if (s >= SEQ) break;
        size_t tok = (size_t)(b * SEQ + s);
        float qv = qkv[tok * 768 + h * DH + lane];
        float m = qv;
        #pragma unroll
        for (int o = 16; o > 0; o >>= 1) m = fmaxf(m, __shfl_xor_sync(0xffffffffu, m, o));
        float e = expf(qv - m);
        float su = e;
        #pragma unroll
        for (int o = 16; o > 0; o >>= 1) su += __shfl_xor_sync(0xffffffffu, su, o);
        float qn = e / su * 0.17677669529663687f;
        float acc = 0.f;
        #pragma unroll
        for (int d = 0; d < DH; d++)
            acc += __shfl_sync(0xffffffffu, qn, d) * cs[h * 1024 + d * 32 + lane];
        size_t o = tok * EMB + h * DH + lane;
        __nv_bfloat16 hi = __float2bfloat16(acc);
        ahi[o] = hi;
        alo[o] = __float2bfloat16(acc - __bfloat162float(hi));
    }
}

// ---------------- host orchestration ----------------
extern "C" void kernel_launch(void* const* d_in, const int* in_sizes, int n_in,
                              void* d_out, int out_size) {
    const float* x    = (const float*)d_in[0];
    const unsigned int* mask = (const unsigned int*)d_in[1];
    const int*   off  = (const int*)d_in[2];
    const float* Wp   = (const float*)d_in[3];
    const float* bp   = (const float*)d_in[4];
    const float* ctok = (const float*)d_in[5];
    const float* ln1g = (const float*)d_in[6];
    const float* ln1b = (const float*)d_in[7];
    const float* Wq   = (const float*)d_in[8];
    const float* Wk   = (const float*)d_in[9];
    const float* Wv   = (const float*)d_in[10];
    const float* Wo   = (const float*)d_in[11];
    const float* ln2g = (const float*)d_in[12];
    const float* ln2b = (const float*)d_in[13];
    const float* W1   = (const float*)d_in[14];
    const float* b1   = (const float*)d_in[15];
    const float* W2   = (const float*)d_in[16];
    const float* b2   = (const float*)d_in[17];
    float* out = (float*)d_out;

    cudaFuncSetAttribute(gemm_mma<256, 0, false, false, false>, cudaFuncAttributeMaxDynamicSharedMemorySize, GSMEM);
    cudaFuncSetAttribute(gemm_mma<256, 0, false, true, false>,  cudaFuncAttributeMaxDynamicSharedMemorySize, GSMEM);
    cudaFuncSetAttribute(gemm_mma<256, 1, true, false, true>,   cudaFuncAttributeMaxDynamicSharedMemorySize, GSMEM);
    cudaFuncSetAttribute(gemm_mma<1024, 0, true, true, false>,  cudaFuncAttributeMaxDynamicSharedMemorySize, GSMEM);

    void *p_spec, *p_h, *p_qkv, *p_ctx;
    void *p_hn_hi, *p_hn_lo, *p_at_hi, *p_at_lo, *p_ffn_hi, *p_ffn_lo;
    void *p_wqkv_hi, *p_wqkv_lo, *p_wo_hi, *p_wo_lo, *p_w1_hi, *p_w1_lo, *p_w2_hi, *p_w2_lo;
    cudaGetSymbolAddress(&p_spec, g_spec);
    cudaGetSymbolAddress(&p_h,    g_h);
    cudaGetSymbolAddress(&p_qkv,  g_qkv);
    cudaGetSymbolAddress(&p_ctx,  g_ctx);
    cudaGetSymbolAddress(&p_hn_hi, g_hn_hi);   cudaGetSymbolAddress(&p_hn_lo, g_hn_lo);
    cudaGetSymbolAddress(&p_at_hi, g_at_hi);   cudaGetSymbolAddress(&p_at_lo, g_at_lo);
    cudaGetSymbolAddress(&p_ffn_hi, g_ffn_hi); cudaGetSymbolAddress(&p_ffn_lo, g_ffn_lo);
    cudaGetSymbolAddress(&p_wqkv_hi, g_wqkv_hi); cudaGetSymbolAddress(&p_wqkv_lo, g_wqkv_lo);
    cudaGetSymbolAddress(&p_wo_hi, g_wo_hi);   cudaGetSymbolAddress(&p_wo_lo, g_wo_lo);
    cudaGetSymbolAddress(&p_w1_hi, g_w1_hi);   cudaGetSymbolAddress(&p_w1_lo, g_w1_lo);
    cudaGetSymbolAddress(&p_w2_hi, g_w2_hi);   cudaGetSymbolAddress(&p_w2_lo, g_w2_lo);

    float* h    = (float*)p_h;
    float* qkv  = (float*)p_qkv;
    float* ctx  = (float*)p_ctx;
    float* spec = (float*)p_spec;
    __nv_bfloat16 *hn_hi = (__nv_bfloat16*)p_hn_hi, *hn_lo = (__nv_bfloat16*)p_hn_lo;
    __nv_bfloat16 *at_hi = (__nv_bfloat16*)p_at_hi, *at_lo = (__nv_bfloat16*)p_at_lo;
    __nv_bfloat16 *ffn_hi = (__nv_bfloat16*)p_ffn_hi, *ffn_lo = (__nv_bfloat16*)p_ffn_lo;
    __nv_bfloat16 *wqkv_hi = (__nv_bfloat16*)p_wqkv_hi, *wqkv_lo = (__nv_bfloat16*)p_wqkv_lo;
    __nv_bfloat16 *wo_hi = (__nv_bfloat16*)p_wo_hi, *wo_lo = (__nv_bfloat16*)p_wo_lo;
    __nv_bfloat16 *w1_hi = (__nv_bfloat16*)p_w1_hi, *w1_lo = (__nv_bfloat16*)p_w1_lo;
    __nv_bfloat16 *w2_hi = (__nv_bfloat16*)p_w2_hi, *w2_lo = (__nv_bfloat16*)p_w2_lo;

    // 0) tables + weight prep
    init_tables<<<19, 256>>>();
    prep_qkv<<<dim3(24, 8, 4), 256>>>(Wq, Wk, Wv, wqkv_hi, wqkv_lo);
    prep_w<<<dim3(8, 8, 4),  256>>>(Wo, wo_hi, wo_lo, 256, 256);
    prep_w<<<dim3(32, 8, 4), 256>>>(W1, w1_hi, w1_lo, 256, 1024);
    prep_w<<<dim3(8, 32, 4), 256>>>(W2, w2_hi, w2_lo, 1024, 256);

    // 1) STFT magnitudes (clean + masked)
    stft_kernel<<<2 * NFRAMES, 128>>>(x, mask, spec);

    // 2) embedding: emb_c -> out, emb_m -> h
    embed_kernel<<<M2 / 32, 256>>>(Wp, bp, ctok, off, out, h);

    // 3) transformer layers
    for (int l = 0; l < 4; l++) {
        ln_kernel<<<NTOK / 8, 256>>>(h, ln1g + l * EMB, ln1b + l * EMB, hn_hi, hn_lo);

        gemm_mma<256, 0, false, false, false><<<dim3(6, NTOK / 128), 256, GSMEM>>>(
            hn_hi, hn_lo, wqkv_hi + (size_t)l * 768 * 256, wqkv_lo + (size_t)l * 768 * 256,
            nullptr, nullptr, qkv, nullptr, nullptr, 768);

        ctx_kernel<<<dim3(NHEADS, NB), 256>>>(qkv, ctx);
        attn_kernel<<<dim3((SEQ + 63) / 64, NB), 256>>>(qkv, ctx, at_hi, at_lo);

        gemm_mma<256, 0, false, true, false><<<dim3(2, NTOK / 128), 256, GSMEM>>>(
            at_hi, at_lo, wo_hi + (size_t)l * 65536, wo_lo + (size_t)l * 65536,
            nullptr, h, h, nullptr, nullptr, 256);

        ln_kernel<<<NTOK / 8, 256>>>(h, ln2g + l * EMB, ln2b + l * EMB, hn_hi, hn_lo);

        gemm_mma<256, 1, true, false, true><<<dim3(8, NTOK / 128), 256, GSMEM>>>(
            hn_hi, hn_lo, w1_hi + (size_t)l * 262144, w1_lo + (size_t)l * 262144,
            b1 + (size_t)l * FFD, nullptr, nullptr, ffn_hi, ffn_lo, 1024);

        float* outH = (l == 3) ? (out + (size_t)NTOK * EMB) : h;
        gemm_mma<1024, 0, true, true, false><<<dim3(2, NTOK / 128), 256, GSMEM>>>(
            ffn_hi, ffn_lo, w2_hi + (size_t)l * 262144, w2_lo + (size_t)l * 262144,
            b2 + (size_t)l * EMB, h, outH, nullptr, nullptr, 256);
    }
}